// round 14
// baseline (speedup 1.0000x reference)
#include <cuda_runtime.h>
#include <cuda_fp16.h>
#include <math.h>
#include <stdint.h>

#define Nc 50000
#define Ec 25000
#define Mc 300000
// dims: INPUT=VERTEX=EDGE=256, QUERY=64, NUM_CLASS=10

// ---------------- scratch ----------------
__device__ __half g_vf16[(size_t)Nc * 256];      // vfeat fp16
__device__ float g_qf[(size_t)Nc * 64];          // q fp32
__device__ __half g_aggv[(size_t)Ec * 256];      // aggregated raw vfeat per edge (fp16)
__device__ float g_swd[Ec];
__device__ __half g_ef16[(size_t)Ec * 320];      // cols 0-63 k, 64-319 v (fp16)
__device__ float g_attn[Mc];                     // precomputed attention scores (vlist order)
// composed weights
__device__ float g_wEf[576 * 256];               // [Wve@W1; Wke@Wve@W1; Wvale@Wve@W1] fp32
__device__ float g_wq1[64 * 256];                // Wqv@W1 fp32
__device__ __half g_wEh[576 * 256], g_wEl[576 * 256];
__device__ __half g_wQh[64 * 256], g_wQl[64 * 256];
__device__ float g_bve1[256];                    // Wve@b1 + bve
__device__ float g_qb[64];                       // Wqv@b1 + bqv
__device__ float g_cb1[576];                     // [bve1; Wke@bve1; Wvale@bve1]
__device__ float g_cb2[576];                     // [0; bke; bvale]
// CSR
__device__ int g_ebeg[Ec], g_vbeg[Nc], g_ecnt[Ec], g_vcnt[Nc];
__device__ int g_ecur[Ec], g_vcur[Nc];
__device__ int g_tote, g_totn;
__device__ int g_elist[Mc], g_vlist[Mc], g_vsrc[Mc];

// ---------------- CSR build ----------------
__global__ void zero_cnts_kernel() {
    int i = blockIdx.x * blockDim.x + threadIdx.x;
    if (i < Ec) g_ecnt[i] = 0;
    if (i < Nc) g_vcnt[i] = 0;
    if (i == 0) { g_tote = 0; g_totn = 0; }
}

// 4 edges per thread, int4 loads (MLP=4 through L2 atomics)
__global__ void hist_kernel(const int* __restrict__ in_src, const int* __restrict__ in_dst) {
    int m4 = blockIdx.x * blockDim.x + threadIdx.x;
    if (m4 * 4 >= Mc) return;
    int4 s = ((const int4*)in_src)[m4];
    int4 e = ((const int4*)in_dst)[m4];
    atomicAdd(&g_ecnt[e.x], 1);
    atomicAdd(&g_ecnt[e.y], 1);
    atomicAdd(&g_ecnt[e.z], 1);
    atomicAdd(&g_ecnt[e.w], 1);
    atomicAdd(&g_vcnt[s.x], 1);
    atomicAdd(&g_vcnt[s.y], 1);
    atomicAdd(&g_vcnt[s.z], 1);
    atomicAdd(&g_vcnt[s.w], 1);
}

__global__ void assign_off_kernel() {
    int i = blockIdx.x * blockDim.x + threadIdx.x;
    int lane = threadIdx.x & 31;
    {
        int c = (i < Ec) ? g_ecnt[i] : 0;
        int x = c;
#pragma unroll
        for (int o = 1; o < 32; o <<= 1) {
            int y = __shfl_up_sync(0xffffffffu, x, o);
            if (lane >= o) x += y;
        }
        int wsum = __shfl_sync(0xffffffffu, x, 31);
        int base = 0;
        if (lane == 31 && wsum > 0) base = atomicAdd(&g_tote, wsum);
        base = __shfl_sync(0xffffffffu, base, 31);
        if (i < Ec) { int b = base + x - c; g_ebeg[i] = b; g_ecur[i] = b; }
    }
    {
        int c = (i < Nc) ? g_vcnt[i] : 0;
        int x = c;
#pragma unroll
        for (int o = 1; o < 32; o <<= 1) {
            int y = __shfl_up_sync(0xffffffffu, x, o);
            if (lane >= o) x += y;
        }
        int wsum = __shfl_sync(0xffffffffu, x, 31);
        int base = 0;
        if (lane == 31 && wsum > 0) base = atomicAdd(&g_totn, wsum);
        base = __shfl_sync(0xffffffffu, base, 31);
        if (i < Nc) { int b = base + x - c; g_vbeg[i] = b; g_vcur[i] = b; }
    }
}

// 4 edges per thread, int4 loads
__global__ void scatter_kernel(const int* __restrict__ in_src, const int* __restrict__ in_dst) {
    int m4 = blockIdx.x * blockDim.x + threadIdx.x;
    if (m4 * 4 >= Mc) return;
    int4 s = ((const int4*)in_src)[m4];
    int4 e = ((const int4*)in_dst)[m4];
    int pe0 = atomicAdd(&g_ecur[e.x], 1);
    int pe1 = atomicAdd(&g_ecur[e.y], 1);
    int pe2 = atomicAdd(&g_ecur[e.z], 1);
    int pe3 = atomicAdd(&g_ecur[e.w], 1);
    g_elist[pe0] = s.x; g_elist[pe1] = s.y; g_elist[pe2] = s.z; g_elist[pe3] = s.w;
    int pv0 = atomicAdd(&g_vcur[s.x], 1);
    int pv1 = atomicAdd(&g_vcur[s.y], 1);
    int pv2 = atomicAdd(&g_vcur[s.z], 1);
    int pv3 = atomicAdd(&g_vcur[s.w], 1);
    g_vlist[pv0] = e.x; g_vlist[pv1] = e.y; g_vlist[pv2] = e.z; g_vlist[pv3] = e.w;
    g_vsrc[pv0] = s.x; g_vsrc[pv1] = s.y; g_vsrc[pv2] = s.z; g_vsrc[pv3] = s.w;
}

// ---------------- weight composition (exact fp32) ----------------
__global__ void compose1(const float* __restrict__ Wve, const float* __restrict__ Wqv,
                         const float* __restrict__ W1) {
    int r = blockIdx.x, j = threadIdx.x;
    const float* A; float* C; int rr;
    if (r < 256) { A = Wve; C = g_wEf; rr = r; }
    else { A = Wqv; C = g_wq1; rr = r - 256; }
    float acc = 0.f;
    for (int k = 0; k < 256; k++) acc += A[rr * 256 + k] * W1[k * 256 + j];
    C[rr * 256 + j] = acc;
}

__global__ void compose2(const float* __restrict__ Wke, const float* __restrict__ Wvale) {
    int r = blockIdx.x, j = threadIdx.x;
    const float* A; int rr, outrow;
    if (r < 64) { A = Wke; rr = r; outrow = 256 + r; }
    else { A = Wvale; rr = r - 64; outrow = 320 + rr; }
    float acc = 0.f;
    for (int k = 0; k < 256; k++) acc += A[rr * 256 + k] * g_wEf[k * 256 + j];
    g_wEf[outrow * 256 + j] = acc;
}

__global__ void bias1(const float* __restrict__ Wve, const float* __restrict__ b1,
                      const float* __restrict__ bve, const float* __restrict__ Wqv,
                      const float* __restrict__ bqv) {
    int t = blockIdx.x * blockDim.x + threadIdx.x;
    int gw = t >> 5, lane = t & 31;
    if (gw >= 320) return;
    const float* M; int i; float add; float* dst;
    if (gw < 256) { M = Wve; i = gw; add = bve[i]; dst = &g_bve1[i]; }
    else { M = Wqv; i = gw - 256; add = bqv[i]; dst = &g_qb[i]; }
    float s = 0.f;
    for (int k = lane; k < 256; k += 32) s += M[i * 256 + k] * b1[k];
#pragma unroll
    for (int o = 16; o; o >>= 1) s += __shfl_xor_sync(0xffffffffu, s, o);
    if (lane == 0) *dst = s + add;
}

__global__ void bias2(const float* __restrict__ Wke, const float* __restrict__ Wvale,
                      const float* __restrict__ bke, const float* __restrict__ bvale) {
    int t = blockIdx.x * blockDim.x + threadIdx.x;
    int gw = t >> 5, lane = t & 31;
    if (gw < 320) {
        const float* M; int i; float* dst;
        if (gw < 64) { M = Wke; i = gw; dst = &g_cb1[256 + i]; }
        else { M = Wvale; i = gw - 64; dst = &g_cb1[320 + i]; }
        float s = 0.f;
        for (int k = lane; k < 256; k += 32) s += M[i * 256 + k] * g_bve1[k];
#pragma unroll
        for (int o = 16; o; o >>= 1) s += __shfl_xor_sync(0xffffffffu, s, o);
        if (lane == 0) *dst = s;
    }
    if (t < 256) { g_cb1[t] = g_bve1[t]; g_cb2[t] = 0.f; }
    else if (t < 320) g_cb2[t] = bke[t - 256];
    else if (t < 576) g_cb2[t] = bvale[t - 320];
}

// ---------------- fp32 -> fp16 conversions ----------------
__global__ void split_hl(const float4* __restrict__ src, __half* __restrict__ hi,
                         __half* __restrict__ lo, int n4) {
    int i = blockIdx.x * blockDim.x + threadIdx.x;
    if (i >= n4) return;
    float4 v = src[i];
    __half h0 = __float2half_rn(v.x), h1 = __float2half_rn(v.y);
    __half h2 = __float2half_rn(v.z), h3 = __float2half_rn(v.w);
    __half l0 = __float2half_rn(v.x - __half2float(h0));
    __half l1 = __float2half_rn(v.y - __half2float(h1));
    __half l2 = __float2half_rn(v.z - __half2float(h2));
    __half l3 = __float2half_rn(v.w - __half2float(h3));
    uint2 H, L;
    H.x = ((uint32_t)__half_as_ushort(h1) << 16) | __half_as_ushort(h0);
    H.y = ((uint32_t)__half_as_ushort(h3) << 16) | __half_as_ushort(h2);
    L.x = ((uint32_t)__half_as_ushort(l1) << 16) | __half_as_ushort(l0);
    L.y = ((uint32_t)__half_as_ushort(l3) << 16) | __half_as_ushort(l2);
    *(uint2*)(hi + (size_t)i * 4) = H;
    *(uint2*)(lo + (size_t)i * 4) = L;
}

__global__ void conv_h(const float4* __restrict__ src, __half* __restrict__ dst, int n4) {
    int i = blockIdx.x * blockDim.x + threadIdx.x;
    if (i >= n4) return;
    float4 v = src[i];
    uint2 H;
    H.x = ((uint32_t)__half_as_ushort(__float2half_rn(v.y)) << 16) | __half_as_ushort(__float2half_rn(v.x));
    H.y = ((uint32_t)__half_as_ushort(__float2half_rn(v.w)) << 16) | __half_as_ushort(__float2half_rn(v.z));
    *(uint2*)(dst + (size_t)i * 4) = H;
}

// ---------------- MMA helpers ----------------
__device__ __forceinline__ void mma16816h(float* d, const uint32_t* a, uint32_t b0, uint32_t b1) {
    asm volatile(
        "mma.sync.aligned.m16n8k16.row.col.f32.f16.f16.f32 "
        "{%0,%1,%2,%3},{%4,%5,%6,%7},{%8,%9},{%0,%1,%2,%3};"
        : "+f"(d[0]), "+f"(d[1]), "+f"(d[2]), "+f"(d[3])
        : "r"(a[0]), "r"(a[1]), "r"(a[2]), "r"(a[3]), "r"(b0), "r"(b1));
}

__device__ __forceinline__ void ldsm_x4(uint32_t* r, uint32_t addr) {
    asm volatile("ldmatrix.sync.aligned.m8n8.x4.shared.b16 {%0,%1,%2,%3}, [%4];"
                 : "=r"(r[0]), "=r"(r[1]), "=r"(r[2]), "=r"(r[3]) : "r"(addr));
}

__device__ __forceinline__ uint32_t smem_u32(const void* p) {
    uint32_t a;
    asm("{ .reg .u64 t; cvta.to.shared.u64 t, %1; cvt.u32.u64 %0, t; }" : "=r"(a) : "l"(p));
    return a;
}

__device__ __forceinline__ void cp_async16(uint32_t dst, const void* src, int src_bytes) {
    asm volatile("cp.async.cg.shared.global [%0], [%1], 16, %2;"
                 :: "r"(dst), "l"(src), "r"(src_bytes) : "memory");
}
#define CP_COMMIT() asm volatile("cp.async.commit_group;" ::: "memory")
#define CP_WAIT(n) asm volatile("cp.async.wait_group %0;" :: "n"(n) : "memory")

// ---------------- fp16x2 GEMM: C[M,NOUT] = A[M,256] @ W^T (+epilogue) ----------------
template <int BN, int NOUT, int MODE>
__global__ __launch_bounds__(256) void gemm_f16(
    const __half* __restrict__ A,
    const __half* __restrict__ whi, const __half* __restrict__ wlo,
    const float* __restrict__ bias,
    const float* __restrict__ cb1, const float* __restrict__ cb2,
    const float* __restrict__ swd,
    float* __restrict__ outA, __half* __restrict__ ef16,
    int Mrows) {
    constexpr int WN = BN / 2;
    constexpr int NF = WN / 8;
    constexpr int Ao = 0;
    constexpr int Bho = 5120;
    constexpr int Blo_ = 5120 + 40 * BN;
    constexpr int STG = 5120 + 80 * BN;
    extern __shared__ __half sm[];
    const uint32_t smb = smem_u32(sm);

    int tid = threadIdx.x;
    int lane = tid & 31, wid = tid >> 5;
    int wm = wid & 3, wn = wid >> 2;
    int qr = lane >> 2, qc = (lane & 3) * 2;
    int bm = blockIdx.x * 128, bn = blockIdx.y * BN;

    int a_row = wm * 32 + (lane & 7) + ((lane >> 3) & 1) * 8;
    int a_col = ((lane >> 4) & 1) * 8;
    int b_col = ((lane >> 3) & 1) * 8;
    int b_rowl = (lane & 7) + ((lane >> 4) & 1) * 8;

    float acc[2][NF][4];
#pragma unroll
    for (int mf = 0; mf < 2; mf++)
#pragma unroll
        for (int nf = 0; nf < NF; nf++)
#pragma unroll
            for (int j = 0; j < 4; j++) acc[mf][nf][j] = 0.f;

    auto load_chunk = [&](int ck, int stage) {
        uint32_t base = smb + (uint32_t)stage * (STG * 2);
#pragma unroll
        for (int i = 0; i < 2; i++) {
            int f = tid + i * 256;
            int row = f >> 2, sg = f & 3;
            int ok = (bm + row < Mrows) ? 16 : 0;
            cp_async16(base + (Ao + row * 40 + sg * 8) * 2,
                       A + (size_t)(bm + row) * 256 + ck * 32 + sg * 8, ok);
        }
        for (int f = tid; f < BN * 4; f += 256) {
            int row = f >> 2, sg = f & 3;
            size_t goff = (size_t)(bn + row) * 256 + ck * 32 + sg * 8;
            cp_async16(base + (Bho + row * 40 + sg * 8) * 2, whi + goff, 16);
            cp_async16(base + (Blo_ + row * 40 + sg * 8) * 2, wlo + goff, 16);
        }
    };

    load_chunk(0, 0);
    CP_COMMIT();

    for (int c = 0; c < 8; c++) {
        if (c < 7) {
            load_chunk(c + 1, (c + 1) & 1);
            CP_COMMIT();
            CP_WAIT(1);
        } else {
            CP_WAIT(0);
        }
        __syncthreads();
        uint32_t base = smb + (uint32_t)(c & 1) * (STG * 2);
#pragma unroll
        for (int ks = 0; ks < 32; ks += 16) {
            uint32_t ah[2][4];
#pragma unroll
            for (int mf = 0; mf < 2; mf++) {
                uint32_t off = ((a_row + mf * 16) * 40 + a_col + ks) * 2;
                ldsm_x4(ah[mf], base + Ao * 2 + off);
            }
            uint32_t bh[NF][2], bl[NF][2];
#pragma unroll
            for (int np = 0; np < NF / 2; np++) {
                uint32_t off = ((wn * WN + np * 16 + b_rowl) * 40 + b_col + ks) * 2;
                uint32_t t[4];
                ldsm_x4(t, base + Bho * 2 + off);
                bh[2 * np][0] = t[0]; bh[2 * np][1] = t[1];
                bh[2 * np + 1][0] = t[2]; bh[2 * np + 1][1] = t[3];
                ldsm_x4(t, base + Blo_ * 2 + off);
                bl[2 * np][0] = t[0]; bl[2 * np][1] = t[1];
                bl[2 * np + 1][0] = t[2]; bl[2 * np + 1][1] = t[3];
            }
#pragma unroll
            for (int nf = 0; nf < NF; nf++) {
#pragma unroll
                for (int mf = 0; mf < 2; mf++) {
                    mma16816h(acc[mf][nf], ah[mf], bh[nf][0], bh[nf][1]);
                    mma16816h(acc[mf][nf], ah[mf], bl[nf][0], bl[nf][1]);
                }
            }
        }
        __syncthreads();
    }

#pragma unroll
    for (int mf = 0; mf < 2; mf++) {
#pragma unroll
        for (int nf = 0; nf < NF; nf++) {
            int m0 = bm + wm * 32 + mf * 16 + qr;
            int n0 = bn + wn * WN + nf * 8 + qc;
            if (MODE == 0) {
                float bv0 = bias[n0], bv1 = bias[n0 + 1];
#pragma unroll
                for (int h = 0; h < 2; h++) {
                    int m = m0 + h * 8;
                    if (m >= Mrows) continue;
                    *(float2*)(outA + (size_t)m * NOUT + n0) =
                        make_float2(acc[mf][nf][h * 2] + bv0, acc[mf][nf][h * 2 + 1] + bv1);
                }
            } else {
                float e0 = cb1[n0], e1 = cb1[n0 + 1];
                float f0 = cb2[n0], f1 = cb2[n0 + 1];
#pragma unroll
                for (int h = 0; h < 2; h++) {
                    int m = m0 + h * 8;
                    if (m >= Mrows) continue;
                    float sw = swd[m];
                    float c0 = acc[mf][nf][h * 2] + sw * e0 + f0;
                    float c1 = acc[mf][nf][h * 2 + 1] + sw * e1 + f1;
                    if (n0 < 256) {
                        *(float2*)(outA + (size_t)m * 256 + n0) = make_float2(c0, c1);
                    } else {
                        uint32_t ph = ((uint32_t)__half_as_ushort(__float2half_rn(c1)) << 16) |
                                      __half_as_ushort(__float2half_rn(c0));
                        *(uint32_t*)(ef16 + (size_t)m * 320 + n0 - 256) = ph;
                    }
                }
            }
        }
    }
}

// ---------------- hyperedge aggregation: one warp per edge, uint4 loads ----------------
__global__ __launch_bounds__(256) void edge_agg_kernel(
    const float* __restrict__ vrw, const float* __restrict__ ers) {
    int e = (blockIdx.x * blockDim.x + threadIdx.x) >> 5;
    int lane = threadIdx.x & 31;
    if (e >= Ec) return;
    int beg = g_ebeg[e], cnt = g_ecnt[e];
    float acc[8];
#pragma unroll
    for (int j = 0; j < 8; j++) acc[j] = 0.f;
    float sw = 0.f;
    for (int i = beg; i < beg + cnt; i++) {
        int s = g_elist[i];
        float w = vrw[s];
        sw += w;
        uint4 raw = *(const uint4*)(g_vf16 + (size_t)s * 256 + lane * 8);
        float2 f0 = __half22float2(*(__half2*)&raw.x);
        float2 f1 = __half22float2(*(__half2*)&raw.y);
        float2 f2 = __half22float2(*(__half2*)&raw.z);
        float2 f3 = __half22float2(*(__half2*)&raw.w);
        acc[0] += w * f0.x; acc[1] += w * f0.y;
        acc[2] += w * f1.x; acc[3] += w * f1.y;
        acc[4] += w * f2.x; acc[5] += w * f2.y;
        acc[6] += w * f3.x; acc[7] += w * f3.y;
    }
    float inv = 1.f / ers[e];
    __half2 o[4];
#pragma unroll
    for (int j = 0; j < 4; j++)
        o[j] = __floats2half2_rn(acc[2 * j] * inv, acc[2 * j + 1] * inv);
    *(uint4*)(g_aggv + (size_t)e * 256 + lane * 8) = *(uint4*)o;
    if (lane == 0) g_swd[e] = sw * inv;
}

// ---------------- attention scores: edge-parallel (8 lanes/edge) ----------------
__global__ __launch_bounds__(256) void attn_score_kernel() {
    int t = blockIdx.x * 256 + threadIdx.x;
    int warp = t >> 5, lane = t & 31;
    int grp = lane >> 3, sub = lane & 7;
    int i = warp * 4 + grp;
    if (i >= Mc) return;
    int s = g_vsrc[i];
    int e = g_vlist[i];
    const float* q = g_qf + (size_t)s * 64 + sub * 8;
    float4 qa = *(const float4*)q;
    float4 qb = *(const float4*)(q + 4);
    uint4 kr = *(const uint4*)(g_ef16 + (size_t)e * 320 + sub * 8);
    float2 k0 = __half22float2(*(__half2*)&kr.x);
    float2 k1 = __half22float2(*(__half2*)&kr.y);
    float2 k2 = __half22float2(*(__half2*)&kr.z);
    float2 k3 = __half22float2(*(__half2*)&kr.w);
    float d = qa.x * k0.x + qa.y * k0.y + qa.z * k1.x + qa.w * k1.y +
              qb.x * k2.x + qb.y * k2.y + qb.z * k3.x + qb.w * k3.y;
    d += __shfl_xor_sync(0xffffffffu, d, 1);
    d += __shfl_xor_sync(0xffffffffu, d, 2);
    d += __shfl_xor_sync(0xffffffffu, d, 4);
    if (sub == 0) {
        d = (d > 0.f ? d : 0.01f * d) * 0.125f;
        g_attn[i] = d;
    }
}

// ---------------- attention accumulate + fused classification head ----------------
__global__ __launch_bounds__(256) void attn_accum_pred_kernel(
    float* __restrict__ out_fv,
    const float* __restrict__ Wc, const float* __restrict__ bc,
    float* __restrict__ pred) {
    int gw = (blockIdx.x * blockDim.x + threadIdx.x) >> 5;
    int lane = threadIdx.x & 31;
    if (gw >= Nc) return;
    int beg = g_vbeg[gw], cnt = g_vcnt[gw];

    float mx = -1e30f;
    for (int base = 0; base < cnt; base += 32) {
        int i = base + lane;
        if (i < cnt) mx = fmaxf(mx, g_attn[beg + i]);
    }
#pragma unroll
    for (int o = 16; o; o >>= 1) mx = fmaxf(mx, __shfl_xor_sync(0xffffffffu, mx, o));

    float denom = 0.f;
    float acc[8];
#pragma unroll
    for (int j = 0; j < 8; j++) acc[j] = 0.f;
#pragma unroll 2
    for (int i = beg; i < beg + cnt; i++) {
        float p = __expf(g_attn[i] - mx);
        denom += p;
        int e = g_vlist[i];
        uint4 raw = *(const uint4*)(g_ef16 + (size_t)e * 320 + 64 + lane * 8);
        float2 f0 = __half22float2(*(__half2*)&raw.x);
        float2 f1 = __half22float2(*(__half2*)&raw.y);
        float2 f2 = __half22float2(*(__half2*)&raw.z);
        float2 f3 = __half22float2(*(__half2*)&raw.w);
        acc[0] += p * f0.x; acc[1] += p * f0.y;
        acc[2] += p * f1.x; acc[3] += p * f1.y;
        acc[4] += p * f2.x; acc[5] += p * f2.y;
        acc[6] += p * f3.x; acc[7] += p * f3.y;
    }
    float inv = 1.f / fmaxf(denom, 1e-20f);
#pragma unroll
    for (int j = 0; j < 8; j++) acc[j] *= inv;
    float4* op = (float4*)(out_fv + (size_t)gw * 256 + lane * 8);
    op[0] = make_float4(acc[0], acc[1], acc[2], acc[3]);
    op[1] = make_float4(acc[4], acc[5], acc[6], acc[7]);

    // fused pred: pred[gw][c] = sum_k fv[k]*Wc[c][k] + bc[c]; lane owns cols lane*8..+7
    float pr[10];
#pragma unroll
    for (int c = 0; c < 10; c++) {
        const float* wr = Wc + c * 256 + lane * 8;
        float s = acc[0] * wr[0] + acc[1] * wr[1] + acc[2] * wr[2] + acc[3] * wr[3] +
                  acc[4] * wr[4] + acc[5] * wr[5] + acc[6] * wr[6] + acc[7] * wr[7];
#pragma unroll
        for (int o = 16; o; o >>= 1) s += __shfl_xor_sync(0xffffffffu, s, o);
        pr[c] = s;
    }
    if (lane < 10) pred[(size_t)gw * 10 + lane] = pr[lane] + bc[lane];
}

// ---------------- launch ----------------
extern "C" void kernel_launch(void* const* d_in, const int* in_sizes, int n_in,
                              void* d_out, int out_size) {
    const float* vfeat = (const float*)d_in[0];
    const float* vrw = (const float*)d_in[2];
    const float* ers = (const float*)d_in[5];
    const float* W1 = (const float*)d_in[6];
    const float* b1 = (const float*)d_in[7];
    const float* Wve = (const float*)d_in[8];
    const float* bve = (const float*)d_in[9];
    const float* Wqv = (const float*)d_in[10];
    const float* bqv = (const float*)d_in[11];
    const float* Wke = (const float*)d_in[12];
    const float* bke = (const float*)d_in[13];
    const float* Wvale = (const float*)d_in[14];
    const float* bvale = (const float*)d_in[15];
    const float* Wcls = (const float*)d_in[16];
    const float* bcls = (const float*)d_in[17];
    const int* in_src = (const int*)d_in[18];
    const int* in_dst = (const int*)d_in[19];

    float* out = (float*)d_out;
    float* out_fv = out;
    float* out_fe = out + (size_t)Nc * 256;
    float* out_pred = out_fe + (size_t)Ec * 256;

    __half *p_vf16, *p_aggv, *p_wEh, *p_wEl, *p_wQh, *p_wQl, *p_ef16;
    float *p_wEf, *p_wq1, *p_qf, *p_qb, *p_cb1, *p_cb2, *p_swd;
    cudaGetSymbolAddress((void**)&p_vf16, g_vf16);
    cudaGetSymbolAddress((void**)&p_aggv, g_aggv);
    cudaGetSymbolAddress((void**)&p_wEh, g_wEh);
    cudaGetSymbolAddress((void**)&p_wEl, g_wEl);
    cudaGetSymbolAddress((void**)&p_wQh, g_wQh);
    cudaGetSymbolAddress((void**)&p_wQl, g_wQl);
    cudaGetSymbolAddress((void**)&p_ef16, g_ef16);
    cudaGetSymbolAddress((void**)&p_wEf, g_wEf);
    cudaGetSymbolAddress((void**)&p_wq1, g_wq1);
    cudaGetSymbolAddress((void**)&p_qf, g_qf);
    cudaGetSymbolAddress((void**)&p_qb, g_qb);
    cudaGetSymbolAddress((void**)&p_cb1, g_cb1);
    cudaGetSymbolAddress((void**)&p_cb2, g_cb2);
    cudaGetSymbolAddress((void**)&p_swd, g_swd);

    const int SMEM64 = 2 * (5120 + 80 * 64) * 2;   // 40960 B
    const int SMEM96 = 2 * (5120 + 80 * 96) * 2;   // 51200 B (> 48KB default: needs attr)

    static cudaStream_t sB = 0, sC = 0;
    static cudaEvent_t ev_fork = 0, ev_csr = 0, ev_conv = 0, ev_w = 0, ev_q = 0;
    static int stream_ok = -1;
    if (stream_ok < 0) {
        cudaFuncSetAttribute(gemm_f16<96, 576, 1>, cudaFuncAttributeMaxDynamicSharedMemorySize, SMEM96);
        cudaFuncSetAttribute(gemm_f16<64, 64, 0>, cudaFuncAttributeMaxDynamicSharedMemorySize, SMEM64);
        cudaError_t e1 = cudaStreamCreateWithFlags(&sB, cudaStreamNonBlocking);
        cudaError_t e2 = cudaStreamCreateWithFlags(&sC, cudaStreamNonBlocking);
        cudaError_t e3 = cudaEventCreateWithFlags(&ev_fork, cudaEventDisableTiming);
        cudaError_t e4 = cudaEventCreateWithFlags(&ev_csr, cudaEventDisableTiming);
        cudaError_t e5 = cudaEventCreateWithFlags(&ev_conv, cudaEventDisableTiming);
        cudaError_t e6 = cudaEventCreateWithFlags(&ev_w, cudaEventDisableTiming);
        cudaError_t e7 = cudaEventCreateWithFlags(&ev_q, cudaEventDisableTiming);
        stream_ok = (e1 == cudaSuccess && e2 == cudaSuccess && e3 == cudaSuccess &&
                     e4 == cudaSuccess && e5 == cudaSuccess && e6 == cudaSuccess &&
                     e7 == cudaSuccess) ? 1 : 0;
    }
    cudaStream_t sb = stream_ok ? sB : 0;
    cudaStream_t sc = stream_ok ? sC : 0;

    if (stream_ok) {
        cudaEventRecord(ev_fork, 0);
        cudaStreamWaitEvent(sB, ev_fork, 0);
        cudaStreamWaitEvent(sC, ev_fork, 0);
    }

    // stream B: CSR build (Mc divisible by 4: 4 edges per thread)
    zero_cnts_kernel<<<(Nc + 255) / 256, 256, 0, sb>>>();
    hist_kernel<<<(Mc / 4 + 255) / 256, 256, 0, sb>>>(in_src, in_dst);
    assign_off_kernel<<<(Nc + 255) / 256, 256, 0, sb>>>();
    scatter_kernel<<<(Mc / 4 + 255) / 256, 256, 0, sb>>>(in_src, in_dst);
    if (stream_ok) cudaEventRecord(ev_csr, sB);

    const int gN = (Nc + 127) / 128;  // 391
    const int gE = (Ec + 127) / 128;  // 196

    // main: vfeat conversion
    conv_h<<<(Nc * 64 + 255) / 256, 256>>>((const float4*)vfeat, p_vf16, Nc * 64);
    if (stream_ok) cudaEventRecord(ev_conv, 0);

    // stream C: weight composition + splits; record ev_w, then q GEMM
    compose1<<<320, 256, 0, sc>>>(Wve, Wqv, W1);
    bias1<<<40, 256, 0, sc>>>(Wve, b1, bve, Wqv, bqv);
    compose2<<<320, 256, 0, sc>>>(Wke, Wvale);
    bias2<<<40, 256, 0, sc>>>(Wke, Wvale, bke, bvale);
    split_hl<<<(576 * 64 + 255) / 256, 256, 0, sc>>>((const float4*)p_wEf, p_wEh, p_wEl, 576 * 64);
    split_hl<<<(64 * 64 + 255) / 256, 256, 0, sc>>>((const float4*)p_wq1, p_wQh, p_wQl, 64 * 64);
    if (stream_ok) cudaEventRecord(ev_w, sC);
    if (stream_ok) cudaStreamWaitEvent(sC, ev_conv, 0);
    gemm_f16<64, 64, 0><<<dim3(gN, 1), 256, SMEM64, sc>>>(
        p_vf16, p_wQh, p_wQl, p_qb, nullptr, nullptr, nullptr, p_qf, nullptr, Nc);
    if (stream_ok) cudaEventRecord(ev_q, sC);

    // main: edge aggregation (needs vf16 + CSR); warp per edge
    if (stream_ok) cudaStreamWaitEvent(0, ev_csr, 0);
    edge_agg_kernel<<<(Ec * 32 + 255) / 256, 256>>>(vrw, ers);
    // GEMM-E needs composed/split weights
    if (stream_ok) cudaStreamWaitEvent(0, ev_w, 0);
    gemm_f16<96, 576, 1><<<dim3(gE, 6), 256, SMEM96>>>(
        p_aggv, p_wEh, p_wEl, nullptr, p_cb1, p_cb2, p_swd, out_fe, p_ef16, Ec);
    // attention: scores, then accumulate with fused classification head
    if (stream_ok) cudaStreamWaitEvent(0, ev_q, 0);
    attn_score_kernel<<<(Mc + 31) / 32, 256>>>();
    attn_accum_pred_kernel<<<(Nc + 7) / 8, 256>>>(out_fv, Wcls, bcls, out_pred);
}

// round 15
// speedup vs baseline: 1.3109x; 1.3109x over previous
#include <cuda_runtime.h>
#include <cuda_fp16.h>
#include <math.h>
#include <stdint.h>

#define Nc 50000
#define Ec 25000
#define Mc 300000
// dims: INPUT=VERTEX=EDGE=256, QUERY=64, NUM_CLASS=10

// ---------------- scratch ----------------
__device__ __half g_vf16[(size_t)Nc * 256];      // vfeat fp16
__device__ float g_qf[(size_t)Nc * 64];          // q fp32
__device__ __half g_aggv[(size_t)Ec * 256];      // aggregated raw vfeat per edge (fp16)
__device__ float g_swd[Ec];
__device__ __half g_ef16[(size_t)Ec * 320];      // cols 0-63 k, 64-319 v (fp16)
__device__ float g_attn[Mc];                     // precomputed attention scores (vlist order)
// composed weights
__device__ float g_wEf[576 * 256];               // [Wve@W1; Wke@Wve@W1; Wvale@Wve@W1] fp32
__device__ float g_wq1[64 * 256];                // Wqv@W1 fp32
__device__ __half g_wEh[576 * 256], g_wEl[576 * 256];
__device__ __half g_wQh[64 * 256], g_wQl[64 * 256];
__device__ float g_bve1[256];                    // Wve@b1 + bve
__device__ float g_qb[64];                       // Wqv@b1 + bqv
__device__ float g_cb1[576];                     // [bve1; Wke@bve1; Wvale@bve1]
__device__ float g_cb2[576];                     // [0; bke; bvale]
// CSR
__device__ int g_ebeg[Ec], g_vbeg[Nc], g_ecnt[Ec], g_vcnt[Nc];
__device__ int g_ecur[Ec], g_vcur[Nc];
__device__ int g_tote, g_totn;
__device__ int g_elist[Mc], g_vlist[Mc], g_vsrc[Mc];

// ---------------- CSR build ----------------
__global__ void zero_cnts_kernel() {
    int i = blockIdx.x * blockDim.x + threadIdx.x;
    if (i < Ec) g_ecnt[i] = 0;
    if (i < Nc) g_vcnt[i] = 0;
    if (i == 0) { g_tote = 0; g_totn = 0; }
}

// 4 edges per thread, int4 loads
__global__ void hist_kernel(const int* __restrict__ in_src, const int* __restrict__ in_dst) {
    int m4 = blockIdx.x * blockDim.x + threadIdx.x;
    if (m4 * 4 >= Mc) return;
    int4 s = ((const int4*)in_src)[m4];
    int4 e = ((const int4*)in_dst)[m4];
    atomicAdd(&g_ecnt[e.x], 1);
    atomicAdd(&g_ecnt[e.y], 1);
    atomicAdd(&g_ecnt[e.z], 1);
    atomicAdd(&g_ecnt[e.w], 1);
    atomicAdd(&g_vcnt[s.x], 1);
    atomicAdd(&g_vcnt[s.y], 1);
    atomicAdd(&g_vcnt[s.z], 1);
    atomicAdd(&g_vcnt[s.w], 1);
}

__global__ void assign_off_kernel() {
    int i = blockIdx.x * blockDim.x + threadIdx.x;
    int lane = threadIdx.x & 31;
    {
        int c = (i < Ec) ? g_ecnt[i] : 0;
        int x = c;
#pragma unroll
        for (int o = 1; o < 32; o <<= 1) {
            int y = __shfl_up_sync(0xffffffffu, x, o);
            if (lane >= o) x += y;
        }
        int wsum = __shfl_sync(0xffffffffu, x, 31);
        int base = 0;
        if (lane == 31 && wsum > 0) base = atomicAdd(&g_tote, wsum);
        base = __shfl_sync(0xffffffffu, base, 31);
        if (i < Ec) { int b = base + x - c; g_ebeg[i] = b; g_ecur[i] = b; }
    }
    {
        int c = (i < Nc) ? g_vcnt[i] : 0;
        int x = c;
#pragma unroll
        for (int o = 1; o < 32; o <<= 1) {
            int y = __shfl_up_sync(0xffffffffu, x, o);
            if (lane >= o) x += y;
        }
        int wsum = __shfl_sync(0xffffffffu, x, 31);
        int base = 0;
        if (lane == 31 && wsum > 0) base = atomicAdd(&g_totn, wsum);
        base = __shfl_sync(0xffffffffu, base, 31);
        if (i < Nc) { int b = base + x - c; g_vbeg[i] = b; g_vcur[i] = b; }
    }
}

// 4 edges per thread, int4 loads
__global__ void scatter_kernel(const int* __restrict__ in_src, const int* __restrict__ in_dst) {
    int m4 = blockIdx.x * blockDim.x + threadIdx.x;
    if (m4 * 4 >= Mc) return;
    int4 s = ((const int4*)in_src)[m4];
    int4 e = ((const int4*)in_dst)[m4];
    int pe0 = atomicAdd(&g_ecur[e.x], 1);
    int pe1 = atomicAdd(&g_ecur[e.y], 1);
    int pe2 = atomicAdd(&g_ecur[e.z], 1);
    int pe3 = atomicAdd(&g_ecur[e.w], 1);
    g_elist[pe0] = s.x; g_elist[pe1] = s.y; g_elist[pe2] = s.z; g_elist[pe3] = s.w;
    int pv0 = atomicAdd(&g_vcur[s.x], 1);
    int pv1 = atomicAdd(&g_vcur[s.y], 1);
    int pv2 = atomicAdd(&g_vcur[s.z], 1);
    int pv3 = atomicAdd(&g_vcur[s.w], 1);
    g_vlist[pv0] = e.x; g_vlist[pv1] = e.y; g_vlist[pv2] = e.z; g_vlist[pv3] = e.w;
    g_vsrc[pv0] = s.x; g_vsrc[pv1] = s.y; g_vsrc[pv2] = s.z; g_vsrc[pv3] = s.w;
}

// ---------------- weight composition (exact fp32) ----------------
__global__ void compose1(const float* __restrict__ Wve, const float* __restrict__ Wqv,
                         const float* __restrict__ W1) {
    int r = blockIdx.x, j = threadIdx.x;
    const float* A; float* C; int rr;
    if (r < 256) { A = Wve; C = g_wEf; rr = r; }
    else { A = Wqv; C = g_wq1; rr = r - 256; }
    float acc = 0.f;
    for (int k = 0; k < 256; k++) acc += A[rr * 256 + k] * W1[k * 256 + j];
    C[rr * 256 + j] = acc;
}

__global__ void compose2(const float* __restrict__ Wke, const float* __restrict__ Wvale) {
    int r = blockIdx.x, j = threadIdx.x;
    const float* A; int rr, outrow;
    if (r < 64) { A = Wke; rr = r; outrow = 256 + r; }
    else { A = Wvale; rr = r - 64; outrow = 320 + rr; }
    float acc = 0.f;
    for (int k = 0; k < 256; k++) acc += A[rr * 256 + k] * g_wEf[k * 256 + j];
    g_wEf[outrow * 256 + j] = acc;
}

__global__ void bias1(const float* __restrict__ Wve, const float* __restrict__ b1,
                      const float* __restrict__ bve, const float* __restrict__ Wqv,
                      const float* __restrict__ bqv) {
    int t = blockIdx.x * blockDim.x + threadIdx.x;
    int gw = t >> 5, lane = t & 31;
    if (gw >= 320) return;
    const float* M; int i; float add; float* dst;
    if (gw < 256) { M = Wve; i = gw; add = bve[i]; dst = &g_bve1[i]; }
    else { M = Wqv; i = gw - 256; add = bqv[i]; dst = &g_qb[i]; }
    float s = 0.f;
    for (int k = lane; k < 256; k += 32) s += M[i * 256 + k] * b1[k];
#pragma unroll
    for (int o = 16; o; o >>= 1) s += __shfl_xor_sync(0xffffffffu, s, o);
    if (lane == 0) *dst = s + add;
}

__global__ void bias2(const float* __restrict__ Wke, const float* __restrict__ Wvale,
                      const float* __restrict__ bke, const float* __restrict__ bvale) {
    int t = blockIdx.x * blockDim.x + threadIdx.x;
    int gw = t >> 5, lane = t & 31;
    if (gw < 320) {
        const float* M; int i; float* dst;
        if (gw < 64) { M = Wke; i = gw; dst = &g_cb1[256 + i]; }
        else { M = Wvale; i = gw - 64; dst = &g_cb1[320 + i]; }
        float s = 0.f;
        for (int k = lane; k < 256; k += 32) s += M[i * 256 + k] * g_bve1[k];
#pragma unroll
        for (int o = 16; o; o >>= 1) s += __shfl_xor_sync(0xffffffffu, s, o);
        if (lane == 0) *dst = s;
    }
    if (t < 256) { g_cb1[t] = g_bve1[t]; g_cb2[t] = 0.f; }
    else if (t < 320) g_cb2[t] = bke[t - 256];
    else if (t < 576) g_cb2[t] = bvale[t - 320];
}

// ---------------- fp32 -> fp16 conversions ----------------
__global__ void split_hl(const float4* __restrict__ src, __half* __restrict__ hi,
                         __half* __restrict__ lo, int n4) {
    int i = blockIdx.x * blockDim.x + threadIdx.x;
    if (i >= n4) return;
    float4 v = src[i];
    __half h0 = __float2half_rn(v.x), h1 = __float2half_rn(v.y);
    __half h2 = __float2half_rn(v.z), h3 = __float2half_rn(v.w);
    __half l0 = __float2half_rn(v.x - __half2float(h0));
    __half l1 = __float2half_rn(v.y - __half2float(h1));
    __half l2 = __float2half_rn(v.z - __half2float(h2));
    __half l3 = __float2half_rn(v.w - __half2float(h3));
    uint2 H, L;
    H.x = ((uint32_t)__half_as_ushort(h1) << 16) | __half_as_ushort(h0);
    H.y = ((uint32_t)__half_as_ushort(h3) << 16) | __half_as_ushort(h2);
    L.x = ((uint32_t)__half_as_ushort(l1) << 16) | __half_as_ushort(l0);
    L.y = ((uint32_t)__half_as_ushort(l3) << 16) | __half_as_ushort(l2);
    *(uint2*)(hi + (size_t)i * 4) = H;
    *(uint2*)(lo + (size_t)i * 4) = L;
}

__global__ void conv_h(const float4* __restrict__ src, __half* __restrict__ dst, int n4) {
    int i = blockIdx.x * blockDim.x + threadIdx.x;
    if (i >= n4) return;
    float4 v = src[i];
    uint2 H;
    H.x = ((uint32_t)__half_as_ushort(__float2half_rn(v.y)) << 16) | __half_as_ushort(__float2half_rn(v.x));
    H.y = ((uint32_t)__half_as_ushort(__float2half_rn(v.w)) << 16) | __half_as_ushort(__float2half_rn(v.z));
    *(uint2*)(dst + (size_t)i * 4) = H;
}

// ---------------- MMA helpers ----------------
__device__ __forceinline__ void mma16816h(float* d, const uint32_t* a, uint32_t b0, uint32_t b1) {
    asm volatile(
        "mma.sync.aligned.m16n8k16.row.col.f32.f16.f16.f32 "
        "{%0,%1,%2,%3},{%4,%5,%6,%7},{%8,%9},{%0,%1,%2,%3};"
        : "+f"(d[0]), "+f"(d[1]), "+f"(d[2]), "+f"(d[3])
        : "r"(a[0]), "r"(a[1]), "r"(a[2]), "r"(a[3]), "r"(b0), "r"(b1));
}

__device__ __forceinline__ void ldsm_x4(uint32_t* r, uint32_t addr) {
    asm volatile("ldmatrix.sync.aligned.m8n8.x4.shared.b16 {%0,%1,%2,%3}, [%4];"
                 : "=r"(r[0]), "=r"(r[1]), "=r"(r[2]), "=r"(r[3]) : "r"(addr));
}

__device__ __forceinline__ uint32_t smem_u32(const void* p) {
    uint32_t a;
    asm("{ .reg .u64 t; cvta.to.shared.u64 t, %1; cvt.u32.u64 %0, t; }" : "=r"(a) : "l"(p));
    return a;
}

__device__ __forceinline__ void cp_async16(uint32_t dst, const void* src, int src_bytes) {
    asm volatile("cp.async.cg.shared.global [%0], [%1], 16, %2;"
                 :: "r"(dst), "l"(src), "r"(src_bytes) : "memory");
}
#define CP_COMMIT() asm volatile("cp.async.commit_group;" ::: "memory")
#define CP_WAIT(n) asm volatile("cp.async.wait_group %0;" :: "n"(n) : "memory")

// ---------------- fp16x2 GEMM: C[M,NOUT] = A[M,256] @ W^T (+epilogue) ----------------
template <int BN, int NOUT, int MODE>
__global__ __launch_bounds__(256) void gemm_f16(
    const __half* __restrict__ A,
    const __half* __restrict__ whi, const __half* __restrict__ wlo,
    const float* __restrict__ bias,
    const float* __restrict__ cb1, const float* __restrict__ cb2,
    const float* __restrict__ swd,
    float* __restrict__ outA, __half* __restrict__ ef16,
    int Mrows) {
    constexpr int WN = BN / 2;
    constexpr int NF = WN / 8;
    constexpr int Ao = 0;
    constexpr int Bho = 5120;
    constexpr int Blo_ = 5120 + 40 * BN;
    constexpr int STG = 5120 + 80 * BN;
    extern __shared__ __half sm[];
    const uint32_t smb = smem_u32(sm);

    int tid = threadIdx.x;
    int lane = tid & 31, wid = tid >> 5;
    int wm = wid & 3, wn = wid >> 2;
    int qr = lane >> 2, qc = (lane & 3) * 2;
    int bm = blockIdx.x * 128, bn = blockIdx.y * BN;

    int a_row = wm * 32 + (lane & 7) + ((lane >> 3) & 1) * 8;
    int a_col = ((lane >> 4) & 1) * 8;
    int b_col = ((lane >> 3) & 1) * 8;
    int b_rowl = (lane & 7) + ((lane >> 4) & 1) * 8;

    float acc[2][NF][4];
#pragma unroll
    for (int mf = 0; mf < 2; mf++)
#pragma unroll
        for (int nf = 0; nf < NF; nf++)
#pragma unroll
            for (int j = 0; j < 4; j++) acc[mf][nf][j] = 0.f;

    auto load_chunk = [&](int ck, int stage) {
        uint32_t base = smb + (uint32_t)stage * (STG * 2);
#pragma unroll
        for (int i = 0; i < 2; i++) {
            int f = tid + i * 256;
            int row = f >> 2, sg = f & 3;
            int ok = (bm + row < Mrows) ? 16 : 0;
            cp_async16(base + (Ao + row * 40 + sg * 8) * 2,
                       A + (size_t)(bm + row) * 256 + ck * 32 + sg * 8, ok);
        }
        for (int f = tid; f < BN * 4; f += 256) {
            int row = f >> 2, sg = f & 3;
            size_t goff = (size_t)(bn + row) * 256 + ck * 32 + sg * 8;
            cp_async16(base + (Bho + row * 40 + sg * 8) * 2, whi + goff, 16);
            cp_async16(base + (Blo_ + row * 40 + sg * 8) * 2, wlo + goff, 16);
        }
    };

    load_chunk(0, 0);
    CP_COMMIT();

    for (int c = 0; c < 8; c++) {
        if (c < 7) {
            load_chunk(c + 1, (c + 1) & 1);
            CP_COMMIT();
            CP_WAIT(1);
        } else {
            CP_WAIT(0);
        }
        __syncthreads();
        uint32_t base = smb + (uint32_t)(c & 1) * (STG * 2);
#pragma unroll
        for (int ks = 0; ks < 32; ks += 16) {
            uint32_t ah[2][4];
#pragma unroll
            for (int mf = 0; mf < 2; mf++) {
                uint32_t off = ((a_row + mf * 16) * 40 + a_col + ks) * 2;
                ldsm_x4(ah[mf], base + Ao * 2 + off);
            }
            uint32_t bh[NF][2], bl[NF][2];
#pragma unroll
            for (int np = 0; np < NF / 2; np++) {
                uint32_t off = ((wn * WN + np * 16 + b_rowl) * 40 + b_col + ks) * 2;
                uint32_t t[4];
                ldsm_x4(t, base + Bho * 2 + off);
                bh[2 * np][0] = t[0]; bh[2 * np][1] = t[1];
                bh[2 * np + 1][0] = t[2]; bh[2 * np + 1][1] = t[3];
                ldsm_x4(t, base + Blo_ * 2 + off);
                bl[2 * np][0] = t[0]; bl[2 * np][1] = t[1];
                bl[2 * np + 1][0] = t[2]; bl[2 * np + 1][1] = t[3];
            }
#pragma unroll
            for (int nf = 0; nf < NF; nf++) {
#pragma unroll
                for (int mf = 0; mf < 2; mf++) {
                    mma16816h(acc[mf][nf], ah[mf], bh[nf][0], bh[nf][1]);
                    mma16816h(acc[mf][nf], ah[mf], bl[nf][0], bl[nf][1]);
                }
            }
        }
        __syncthreads();
    }

#pragma unroll
    for (int mf = 0; mf < 2; mf++) {
#pragma unroll
        for (int nf = 0; nf < NF; nf++) {
            int m0 = bm + wm * 32 + mf * 16 + qr;
            int n0 = bn + wn * WN + nf * 8 + qc;
            if (MODE == 0) {
                float bv0 = bias[n0], bv1 = bias[n0 + 1];
#pragma unroll
                for (int h = 0; h < 2; h++) {
                    int m = m0 + h * 8;
                    if (m >= Mrows) continue;
                    *(float2*)(outA + (size_t)m * NOUT + n0) =
                        make_float2(acc[mf][nf][h * 2] + bv0, acc[mf][nf][h * 2 + 1] + bv1);
                }
            } else {
                float e0 = cb1[n0], e1 = cb1[n0 + 1];
                float f0 = cb2[n0], f1 = cb2[n0 + 1];
#pragma unroll
                for (int h = 0; h < 2; h++) {
                    int m = m0 + h * 8;
                    if (m >= Mrows) continue;
                    float sw = swd[m];
                    float c0 = acc[mf][nf][h * 2] + sw * e0 + f0;
                    float c1 = acc[mf][nf][h * 2 + 1] + sw * e1 + f1;
                    if (n0 < 256) {
                        *(float2*)(outA + (size_t)m * 256 + n0) = make_float2(c0, c1);
                    } else {
                        uint32_t ph = ((uint32_t)__half_as_ushort(__float2half_rn(c1)) << 16) |
                                      __half_as_ushort(__float2half_rn(c0));
                        *(uint32_t*)(ef16 + (size_t)m * 320 + n0 - 256) = ph;
                    }
                }
            }
        }
    }
}

// ---------------- hyperedge aggregation: one warp per edge, uint4 loads ----------------
__global__ __launch_bounds__(256) void edge_agg_kernel(
    const float* __restrict__ vrw, const float* __restrict__ ers) {
    int e = (blockIdx.x * blockDim.x + threadIdx.x) >> 5;
    int lane = threadIdx.x & 31;
    if (e >= Ec) return;
    int beg = g_ebeg[e], cnt = g_ecnt[e];
    float acc[8];
#pragma unroll
    for (int j = 0; j < 8; j++) acc[j] = 0.f;
    float sw = 0.f;
    for (int i = beg; i < beg + cnt; i++) {
        int s = g_elist[i];
        float w = vrw[s];
        sw += w;
        uint4 raw = *(const uint4*)(g_vf16 + (size_t)s * 256 + lane * 8);
        float2 f0 = __half22float2(*(__half2*)&raw.x);
        float2 f1 = __half22float2(*(__half2*)&raw.y);
        float2 f2 = __half22float2(*(__half2*)&raw.z);
        float2 f3 = __half22float2(*(__half2*)&raw.w);
        acc[0] += w * f0.x; acc[1] += w * f0.y;
        acc[2] += w * f1.x; acc[3] += w * f1.y;
        acc[4] += w * f2.x; acc[5] += w * f2.y;
        acc[6] += w * f3.x; acc[7] += w * f3.y;
    }
    float inv = 1.f / ers[e];
    __half2 o[4];
#pragma unroll
    for (int j = 0; j < 4; j++)
        o[j] = __floats2half2_rn(acc[2 * j] * inv, acc[2 * j + 1] * inv);
    *(uint4*)(g_aggv + (size_t)e * 256 + lane * 8) = *(uint4*)o;
    if (lane == 0) g_swd[e] = sw * inv;
}

// ---------------- attention scores: edge-parallel (8 lanes/edge) ----------------
__global__ __launch_bounds__(256) void attn_score_kernel() {
    int t = blockIdx.x * 256 + threadIdx.x;
    int warp = t >> 5, lane = t & 31;
    int grp = lane >> 3, sub = lane & 7;
    int i = warp * 4 + grp;
    if (i >= Mc) return;
    int s = g_vsrc[i];
    int e = g_vlist[i];
    const float* q = g_qf + (size_t)s * 64 + sub * 8;
    float4 qa = *(const float4*)q;
    float4 qb = *(const float4*)(q + 4);
    uint4 kr = *(const uint4*)(g_ef16 + (size_t)e * 320 + sub * 8);
    float2 k0 = __half22float2(*(__half2*)&kr.x);
    float2 k1 = __half22float2(*(__half2*)&kr.y);
    float2 k2 = __half22float2(*(__half2*)&kr.z);
    float2 k3 = __half22float2(*(__half2*)&kr.w);
    float d = qa.x * k0.x + qa.y * k0.y + qa.z * k1.x + qa.w * k1.y +
              qb.x * k2.x + qb.y * k2.y + qb.z * k3.x + qb.w * k3.y;
    d += __shfl_xor_sync(0xffffffffu, d, 1);
    d += __shfl_xor_sync(0xffffffffu, d, 2);
    d += __shfl_xor_sync(0xffffffffu, d, 4);
    if (sub == 0) {
        d = (d > 0.f ? d : 0.01f * d) * 0.125f;
        g_attn[i] = d;
    }
}

// ---------------- attention accumulate + fused pred (Wcls staged in smem) ----------
__global__ __launch_bounds__(256) void attn_accum_pred_kernel(
    float* __restrict__ out_fv,
    const float* __restrict__ Wc, const float* __restrict__ bc,
    float* __restrict__ pred) {
    __shared__ float sW[10 * 256];
    __shared__ float sb_[10];
    {
        int t = threadIdx.x;
        for (int i = t; i < 2560; i += 256) sW[i] = Wc[i];
        if (t < 10) sb_[t] = bc[t];
    }
    __syncthreads();

    int gw = (blockIdx.x * blockDim.x + threadIdx.x) >> 5;
    int lane = threadIdx.x & 31;
    if (gw >= Nc) return;
    int beg = g_vbeg[gw], cnt = g_vcnt[gw];

    float mx = -1e30f;
    for (int base = 0; base < cnt; base += 32) {
        int i = base + lane;
        if (i < cnt) mx = fmaxf(mx, g_attn[beg + i]);
    }
#pragma unroll
    for (int o = 16; o; o >>= 1) mx = fmaxf(mx, __shfl_xor_sync(0xffffffffu, mx, o));

    float denom = 0.f;
    float acc[8];
#pragma unroll
    for (int j = 0; j < 8; j++) acc[j] = 0.f;
#pragma unroll 2
    for (int i = beg; i < beg + cnt; i++) {
        float p = __expf(g_attn[i] - mx);
        denom += p;
        int e = g_vlist[i];
        uint4 raw = *(const uint4*)(g_ef16 + (size_t)e * 320 + 64 + lane * 8);
        float2 f0 = __half22float2(*(__half2*)&raw.x);
        float2 f1 = __half22float2(*(__half2*)&raw.y);
        float2 f2 = __half22float2(*(__half2*)&raw.z);
        float2 f3 = __half22float2(*(__half2*)&raw.w);
        acc[0] += p * f0.x; acc[1] += p * f0.y;
        acc[2] += p * f1.x; acc[3] += p * f1.y;
        acc[4] += p * f2.x; acc[5] += p * f2.y;
        acc[6] += p * f3.x; acc[7] += p * f3.y;
    }
    float inv = 1.f / fmaxf(denom, 1e-20f);
#pragma unroll
    for (int j = 0; j < 8; j++) acc[j] *= inv;
    float4* op = (float4*)(out_fv + (size_t)gw * 256 + lane * 8);
    op[0] = make_float4(acc[0], acc[1], acc[2], acc[3]);
    op[1] = make_float4(acc[4], acc[5], acc[6], acc[7]);

    // fused pred via smem-staged Wcls: lane owns fv cols lane*8..+7
    float pr[10];
#pragma unroll
    for (int c = 0; c < 10; c++) {
        const float* wr = sW + c * 256 + lane * 8;
        float s = acc[0] * wr[0] + acc[1] * wr[1] + acc[2] * wr[2] + acc[3] * wr[3] +
                  acc[4] * wr[4] + acc[5] * wr[5] + acc[6] * wr[6] + acc[7] * wr[7];
#pragma unroll
        for (int o = 16; o; o >>= 1) s += __shfl_xor_sync(0xffffffffu, s, o);
        pr[c] = s;
    }
    if (lane < 10) pred[(size_t)gw * 10 + lane] = pr[lane] + sb_[lane];
}

// ---------------- launch ----------------
extern "C" void kernel_launch(void* const* d_in, const int* in_sizes, int n_in,
                              void* d_out, int out_size) {
    const float* vfeat = (const float*)d_in[0];
    const float* vrw = (const float*)d_in[2];
    const float* ers = (const float*)d_in[5];
    const float* W1 = (const float*)d_in[6];
    const float* b1 = (const float*)d_in[7];
    const float* Wve = (const float*)d_in[8];
    const float* bve = (const float*)d_in[9];
    const float* Wqv = (const float*)d_in[10];
    const float* bqv = (const float*)d_in[11];
    const float* Wke = (const float*)d_in[12];
    const float* bke = (const float*)d_in[13];
    const float* Wvale = (const float*)d_in[14];
    const float* bvale = (const float*)d_in[15];
    const float* Wcls = (const float*)d_in[16];
    const float* bcls = (const float*)d_in[17];
    const int* in_src = (const int*)d_in[18];
    const int* in_dst = (const int*)d_in[19];

    float* out = (float*)d_out;
    float* out_fv = out;
    float* out_fe = out + (size_t)Nc * 256;
    float* out_pred = out_fe + (size_t)Ec * 256;

    __half *p_vf16, *p_aggv, *p_wEh, *p_wEl, *p_wQh, *p_wQl, *p_ef16;
    float *p_wEf, *p_wq1, *p_qf, *p_qb, *p_cb1, *p_cb2, *p_swd;
    cudaGetSymbolAddress((void**)&p_vf16, g_vf16);
    cudaGetSymbolAddress((void**)&p_aggv, g_aggv);
    cudaGetSymbolAddress((void**)&p_wEh, g_wEh);
    cudaGetSymbolAddress((void**)&p_wEl, g_wEl);
    cudaGetSymbolAddress((void**)&p_wQh, g_wQh);
    cudaGetSymbolAddress((void**)&p_wQl, g_wQl);
    cudaGetSymbolAddress((void**)&p_ef16, g_ef16);
    cudaGetSymbolAddress((void**)&p_wEf, g_wEf);
    cudaGetSymbolAddress((void**)&p_wq1, g_wq1);
    cudaGetSymbolAddress((void**)&p_qf, g_qf);
    cudaGetSymbolAddress((void**)&p_qb, g_qb);
    cudaGetSymbolAddress((void**)&p_cb1, g_cb1);
    cudaGetSymbolAddress((void**)&p_cb2, g_cb2);
    cudaGetSymbolAddress((void**)&p_swd, g_swd);

    const int SMEM64 = 2 * (5120 + 80 * 64) * 2;   // 40960 B
    const int SMEM96 = 2 * (5120 + 80 * 96) * 2;   // 51200 B (> 48KB default: needs attr)

    static cudaStream_t sB = 0, sC = 0;
    static cudaEvent_t ev_fork = 0, ev_csr = 0, ev_conv = 0, ev_w = 0, ev_q = 0;
    static int stream_ok = -1;
    if (stream_ok < 0) {
        cudaFuncSetAttribute(gemm_f16<96, 576, 1>, cudaFuncAttributeMaxDynamicSharedMemorySize, SMEM96);
        cudaFuncSetAttribute(gemm_f16<64, 64, 0>, cudaFuncAttributeMaxDynamicSharedMemorySize, SMEM64);
        cudaError_t e1 = cudaStreamCreateWithFlags(&sB, cudaStreamNonBlocking);
        cudaError_t e2 = cudaStreamCreateWithFlags(&sC, cudaStreamNonBlocking);
        cudaError_t e3 = cudaEventCreateWithFlags(&ev_fork, cudaEventDisableTiming);
        cudaError_t e4 = cudaEventCreateWithFlags(&ev_csr, cudaEventDisableTiming);
        cudaError_t e5 = cudaEventCreateWithFlags(&ev_conv, cudaEventDisableTiming);
        cudaError_t e6 = cudaEventCreateWithFlags(&ev_w, cudaEventDisableTiming);
        cudaError_t e7 = cudaEventCreateWithFlags(&ev_q, cudaEventDisableTiming);
        stream_ok = (e1 == cudaSuccess && e2 == cudaSuccess && e3 == cudaSuccess &&
                     e4 == cudaSuccess && e5 == cudaSuccess && e6 == cudaSuccess &&
                     e7 == cudaSuccess) ? 1 : 0;
    }
    cudaStream_t sb = stream_ok ? sB : 0;
    cudaStream_t sc = stream_ok ? sC : 0;

    if (stream_ok) {
        cudaEventRecord(ev_fork, 0);
        cudaStreamWaitEvent(sB, ev_fork, 0);
        cudaStreamWaitEvent(sC, ev_fork, 0);
    }

    // stream B: CSR build (Mc divisible by 4: 4 edges per thread)
    zero_cnts_kernel<<<(Nc + 255) / 256, 256, 0, sb>>>();
    hist_kernel<<<(Mc / 4 + 255) / 256, 256, 0, sb>>>(in_src, in_dst);
    assign_off_kernel<<<(Nc + 255) / 256, 256, 0, sb>>>();
    scatter_kernel<<<(Mc / 4 + 255) / 256, 256, 0, sb>>>(in_src, in_dst);
    if (stream_ok) cudaEventRecord(ev_csr, sB);

    const int gN = (Nc + 127) / 128;  // 391
    const int gE = (Ec + 127) / 128;  // 196

    // main: vfeat conversion
    conv_h<<<(Nc * 64 + 255) / 256, 256>>>((const float4*)vfeat, p_vf16, Nc * 64);
    if (stream_ok) cudaEventRecord(ev_conv, 0);

    // stream C: weight composition + splits; record ev_w, then q GEMM
    compose1<<<320, 256, 0, sc>>>(Wve, Wqv, W1);
    bias1<<<40, 256, 0, sc>>>(Wve, b1, bve, Wqv, bqv);
    compose2<<<320, 256, 0, sc>>>(Wke, Wvale);
    bias2<<<40, 256, 0, sc>>>(Wke, Wvale, bke, bvale);
    split_hl<<<(576 * 64 + 255) / 256, 256, 0, sc>>>((const float4*)p_wEf, p_wEh, p_wEl, 576 * 64);
    split_hl<<<(64 * 64 + 255) / 256, 256, 0, sc>>>((const float4*)p_wq1, p_wQh, p_wQl, 64 * 64);
    if (stream_ok) cudaEventRecord(ev_w, sC);
    if (stream_ok) cudaStreamWaitEvent(sC, ev_conv, 0);
    gemm_f16<64, 64, 0><<<dim3(gN, 1), 256, SMEM64, sc>>>(
        p_vf16, p_wQh, p_wQl, p_qb, nullptr, nullptr, nullptr, p_qf, nullptr, Nc);
    if (stream_ok) cudaEventRecord(ev_q, sC);

    // main: edge aggregation (needs vf16 + CSR); warp per edge
    if (stream_ok) cudaStreamWaitEvent(0, ev_csr, 0);
    edge_agg_kernel<<<(Ec * 32 + 255) / 256, 256>>>(vrw, ers);
    // GEMM-E needs composed/split weights
    if (stream_ok) cudaStreamWaitEvent(0, ev_w, 0);
    gemm_f16<96, 576, 1><<<dim3(gE, 6), 256, SMEM96>>>(
        p_aggv, p_wEh, p_wEl, nullptr, p_cb1, p_cb2, p_swd, out_fe, p_ef16, Ec);
    // attention: scores, then accumulate with fused (smem-staged) classification head
    if (stream_ok) cudaStreamWaitEvent(0, ev_q, 0);
    attn_score_kernel<<<(Mc + 31) / 32, 256>>>();
    attn_accum_pred_kernel<<<(Nc + 7) / 8, 256>>>(out_fv, Wcls, bcls, out_pred);
}